// round 8
// baseline (speedup 1.0000x reference)
#include <cuda_runtime.h>
#include <cuda_bf16.h>
#include <cstdint>

#define S_LEN  262144
#define NDIM   128
#define TILE   128
#define NTILES 2048
#define NCTA   296        // 2 CTAs/SM x 148 SMs
#define NPROD  128        // producer CTAs for W

// ---------------- device scratch ----------------
__device__ float g_W[NDIM * NDIM];                          // M (fp32, for l1)
__device__ __align__(16) __nv_bfloat16 g_Bsw[NDIM * NDIM];  // B[t][k]=bf16(M[k][t]), swizzled
__device__ float g_partials[NCTA];
__device__ int   g_done;                                     // producer counter (reset by finalize)

// ---------------- smem byte offsets (per CTA ~100KB -> 2 CTAs/SM) ----------------
#define PLN0  0          // bf16 A plane buf0: 128 x 256B = 32768
#define PLN1  32768      // buf1
#define BOF   65536      // B bf16 swizzled: 32768
#define NXT   98304      // boundary row fp32: 512
#define ROWS  98816      // rowsum[128] fp32: 512
#define RED   99328      // reduction: 256 fp32 = 1024
#define SMEM_BYTES 100352

// ---------------- helpers ----------------
__device__ __forceinline__ uint32_t smem_u32(const void* p) {
    uint32_t a;
    asm("{ .reg .u64 t; cvta.to.shared.u64 t, %1; cvt.u32.u64 %0, t; }" : "=r"(a) : "l"(p));
    return a;
}
__device__ __forceinline__ uint32_t bf2(float xh, float xl) {
    uint32_t r;
    asm("cvt.rn.bf16x2.f32 %0, %1, %2;" : "=r"(r) : "f"(xh), "f"(xl));
    return r;
}
__device__ __forceinline__ float lo_f(uint32_t p) { return __uint_as_float(p << 16); }
__device__ __forceinline__ float hi_f(uint32_t p) { return __uint_as_float(p & 0xffff0000u); }

__device__ __forceinline__ uint2 lds64u(uint32_t a) {
    uint2 v;
    asm volatile("ld.shared.v2.b32 {%0,%1}, [%2];" : "=r"(v.x), "=r"(v.y) : "r"(a));
    return v;
}
__device__ __forceinline__ float2 lds64f(uint32_t a) {
    float2 v;
    asm volatile("ld.shared.v2.f32 {%0,%1}, [%2];" : "=f"(v.x), "=f"(v.y) : "r"(a));
    return v;
}
__device__ __forceinline__ uint32_t lds32(uint32_t a) {
    uint32_t v;
    asm volatile("ld.shared.b32 %0, [%1];" : "=r"(v) : "r"(a));
    return v;
}
__device__ __forceinline__ void sts128(uint32_t a, uint32_t x, uint32_t y, uint32_t z, uint32_t w) {
    asm volatile("st.shared.v4.b32 [%0], {%1,%2,%3,%4};" :: "r"(a), "r"(x), "r"(y), "r"(z), "r"(w));
}
__device__ __forceinline__ void mma_bf16(float* d, const uint32_t* a, uint32_t b0, uint32_t b1) {
    asm volatile(
        "mma.sync.aligned.m16n8k16.row.col.f32.bf16.bf16.f32 "
        "{%0,%1,%2,%3}, {%4,%5,%6,%7}, {%8,%9}, {%0,%1,%2,%3};"
        : "+f"(d[0]), "+f"(d[1]), "+f"(d[2]), "+f"(d[3])
        : "r"(a[0]), "r"(a[1]), "r"(a[2]), "r"(a[3]), "r"(b0), "r"(b1));
}
__device__ __forceinline__ float softplusf(float x) {
    const float l = __logf(1.0f + __expf(x));
    return (x > 15.0f) ? x : l;
}
// swizzled byte offset: plane row r (256B rows), element index k
__device__ __forceinline__ uint32_t gsw(int r, int k) {
    return (uint32_t)(r * 256 + (((k >> 2) ^ ((r & 7) << 2)) << 3) + (k & 3) * 2);
}

// ---------------- fused persistent kernel ----------------
extern __shared__ char dsm[];

// LDG fp32 -> rowsums + bf16 plane (swizzled) + boundary row
__device__ __forceinline__ void ldg_pass(const float* __restrict__ In, int tile,
                                         uint32_t pln, int tid) {
    const int r = tid >> 1, h = tid & 1;
    const float4* src = (const float4*)(In + (size_t)tile * TILE * NDIM) + r * 32 + h * 16;
    const uint32_t xr = (uint32_t)((r & 7) << 2);
    const uint32_t base = pln + (uint32_t)r * 256;
    float rs = 0.f;
#pragma unroll
    for (int wv = 0; wv < 4; ++wv) {
        const float4 v0 = __ldcs(src + wv * 4 + 0);
        const float4 v1 = __ldcs(src + wv * 4 + 1);
        const float4 v2 = __ldcs(src + wv * 4 + 2);
        const float4 v3 = __ldcs(src + wv * 4 + 3);
        rs += ((v0.x + v0.y) + (v0.z + v0.w)) + ((v1.x + v1.y) + (v1.z + v1.w))
            + ((v2.x + v2.y) + (v2.z + v2.w)) + ((v3.x + v3.y) + (v3.z + v3.w));
        const uint32_t p0 = (uint32_t)(h * 16 + wv * 4);
        sts128(base + (((p0 ^ xr)) << 3),
               bf2(v0.y, v0.x), bf2(v0.w, v0.z), bf2(v1.y, v1.x), bf2(v1.w, v1.z));
        sts128(base + ((((p0 + 2) ^ xr)) << 3),
               bf2(v2.y, v2.x), bf2(v2.w, v2.z), bf2(v3.y, v3.x), bf2(v3.w, v3.z));
    }
    rs += __shfl_xor_sync(0xffffffffu, rs, 1);
    if (h == 0) ((float*)(dsm + ROWS))[r] = rs;
    if (tid < 32) {   // boundary row = first row of sequentially-next tile
        size_t nr = (size_t)tile * TILE + TILE;
        if (nr >= S_LEN) nr = 0;                 // clamped; value masked in epilogue
        const float4 v = __ldg((const float4*)(In + nr * NDIM) + tid);
        ((float4*)(dsm + NXT))[tid] = v;
    }
}

__global__ void __launch_bounds__(256, 2)
fused_kernel(const float* __restrict__ In, const float* __restrict__ WQ,
             const float* __restrict__ WK) {
    const uint32_t sb = smem_u32(dsm);
    const int tid  = threadIdx.x;
    const int lane = tid & 31;
    const int w    = tid >> 5;
    const int m0   = (w & 3) << 5;     // warp tile: 32m x 64n (grid 4m x 2n)
    const int n0   = (w >> 2) << 6;
    const int g    = lane >> 2;
    const int q    = lane & 3;
    const int bx   = blockIdx.x;

    // ---- producers: CTA c < NPROD computes B row t=c (M[:, c]) ----
    if (bx < NPROD) {
        const int c  = bx;
        const int i  = tid >> 1;      // M row index (k)
        const int jh = tid & 1;
        float acc = 0.f;
#pragma unroll 8
        for (int jj = 0; jj < 64; ++jj) {
            const int j = jh * 64 + jj;
            acc = fmaf(__ldg(WK + j * NDIM + i), __ldg(WQ + j * NDIM + c), acc);
        }
        acc += __shfl_xor_sync(0xffffffffu, acc, 1);
        if (jh == 0) {
            g_W[i * NDIM + c] = acc;
            *(__nv_bfloat16*)((char*)g_Bsw + gsw(c, i)) = __float2bfloat16(acc);
        }
        __threadfence();
        __syncthreads();
        if (tid == 0) atomicAdd(&g_done, 1);
    }

    const int nt = (NTILES - bx + NCTA - 1) / NCTA;

    // ---- first tile load (overlaps producer work on other CTAs) ----
    ldg_pass(In, bx, sb + PLN0, tid);

    // ---- wait for W, stage B ----
    if (tid == 0) {
        int v;
        do {
            asm volatile("ld.acquire.gpu.b32 %0, [%1];" : "=r"(v) : "l"(&g_done) : "memory");
            if (v < NPROD) __nanosleep(64);
        } while (v < NPROD);
    }
    __syncthreads();
    {
        const float4* src = (const float4*)g_Bsw;
        float4* dst = (float4*)(dsm + BOF);
#pragma unroll
        for (int k = tid; k < 2048; k += 256) dst[k] = src[k];
    }
    __syncthreads();    // plane0 + rowsums + B ready

    const uint32_t xg = (uint32_t)(g << 2);
    const int rA0 = m0 + g;
    const uint32_t bB = sb + BOF + (uint32_t)(n0 + g) * 256;

    float loss = 0.f;
    for (int i = 0; i < nt; ++i) {
        const int tile = bx + i * NCTA;
        const uint32_t pcur = sb + ((i & 1) ? PLN1 : PLN0);
        const uint32_t bA = pcur + (uint32_t)rA0 * 256;

        // -------- mainloop: 8 k-steps from bf16 planes --------
        float dacc[2][8][4];
#pragma unroll
        for (int mh = 0; mh < 2; ++mh)
#pragma unroll
            for (int nf = 0; nf < 8; ++nf)
#pragma unroll
                for (int j = 0; j < 4; ++j) dacc[mh][nf][j] = 0.f;

#pragma unroll
        for (int ks = 0; ks < 8; ++ks) {
            const uint32_t off = ((uint32_t)(4 * ks + q) ^ xg) << 3;
            const uint2 r0  = lds64u(bA + off);
            const uint2 r8  = lds64u(bA + 8 * 256 + off);
            const uint2 r16 = lds64u(bA + 16 * 256 + off);
            const uint2 r24 = lds64u(bA + 24 * 256 + off);
            const uint32_t a0[4] = {r0.x,  r8.x,  r0.y,  r8.y};
            const uint32_t a1[4] = {r16.x, r24.x, r16.y, r24.y};
#pragma unroll
            for (int nf = 0; nf < 8; ++nf) {
                const uint2 b = lds64u(bB + (uint32_t)nf * 2048 + off);
                mma_bf16(dacc[0][nf], a0, b.x, b.y);
                mma_bf16(dacc[1][nf], a1, b.x, b.y);
            }
        }

        // -------- epilogue --------
        const float* sRow = (const float*)(dsm + ROWS);
        const size_t base = (size_t)tile * TILE;
#pragma unroll
        for (int mh = 0; mh < 2; ++mh) {
            const int rA = m0 + 16 * mh + g;        // <= 119 (always valid)
            const int rB = rA + 8;                  // <= 127
            const float rsA = sRow[rA];
            const float rsB = sRow[rB];
            const bool vB = (base + rB) < (size_t)(S_LEN - 1);
#pragma unroll
            for (int nf = 0; nf < 8; ++nf) {
                const int col0 = n0 + 8 * nf + 2 * q;     // even
                const uint32_t va = lds32(pcur + gsw(rA + 1, col0));
                const float nxa0 = lo_f(va), nxa1 = hi_f(va);
                float nxb0, nxb1;
                if (rB < TILE - 1) {
                    const uint32_t vb = lds32(pcur + gsw(rB + 1, col0));
                    nxb0 = lo_f(vb); nxb1 = hi_f(vb);
                } else {
                    const float2 nb = lds64f(sb + NXT + col0 * 4);
                    nxb0 = nb.x; nxb1 = nb.y;
                }
                const float* d = dacc[mh][nf];
                const float t0 = fmaf(softplusf(d[0]), rsA, -nxa0);
                const float t1 = fmaf(softplusf(d[1]), rsA, -nxa1);
                loss = fmaf(t0, t0, loss);
                loss = fmaf(t1, t1, loss);
                if (vB) {
                    const float t2 = fmaf(softplusf(d[2]), rsB, -nxb0);
                    const float t3 = fmaf(softplusf(d[3]), rsB, -nxb1);
                    loss = fmaf(t2, t2, loss);
                    loss = fmaf(t3, t3, loss);
                }
            }
        }

        __syncthreads();     // epilogue done reading NXT/ROWS before refill
        if (i + 1 < nt)
            ldg_pass(In, bx + (i + 1) * NCTA, sb + (((i + 1) & 1) ? PLN1 : PLN0), tid);
        __syncthreads();     // next plane ready
    }

    // deterministic CTA reduction
    float* sRed = (float*)(dsm + RED);
    sRed[tid] = loss;
    __syncthreads();
#pragma unroll
    for (int o = 128; o; o >>= 1) {
        if (tid < o) sRed[tid] += sRed[tid + o];
        __syncthreads();
    }
    if (tid == 0) g_partials[bx] = sRed[0];
}

// ---------------- finalize ----------------
__global__ void finalize_kernel(float* __restrict__ out) {
    __shared__ double red[256];
    const int tid = threadIdx.x;

    double s = 0.0;
    for (int k = tid; k < NCTA; k += 256) s += (double)g_partials[k];
    red[tid] = s;
    __syncthreads();
    for (int o = 128; o; o >>= 1) {
        if (tid < o) red[tid] += red[tid + o];
        __syncthreads();
    }
    if (tid == 0)
        out[0] = (float)(red[0] / ((double)(S_LEN - 1) * (double)NDIM));
    __syncthreads();

    double l1 = 0.0;
    for (int k = tid; k < NDIM * NDIM; k += 256) {
        const float w = g_W[k];
        l1 += (double)(1.0f / (1.0f + __expf(-w)));
    }
    red[tid] = l1;
    __syncthreads();
    for (int o = 128; o; o >>= 1) {
        if (tid < o) red[tid] += red[tid + o];
        __syncthreads();
    }
    if (tid == 0) {
        out[1] = (float)red[0];
        g_done = 0;                      // reset flag for next graph replay
    }
}

// ---------------- launch ----------------
extern "C" void kernel_launch(void* const* d_in, const int* in_sizes, int n_in,
                              void* d_out, int out_size) {
    const float* In = (const float*)d_in[0];
    const float* WQ = (const float*)d_in[1];
    const float* WK = (const float*)d_in[2];
    float* out = (float*)d_out;

    cudaFuncSetAttribute(fused_kernel,
                         cudaFuncAttributeMaxDynamicSharedMemorySize, SMEM_BYTES);
    fused_kernel<<<NCTA, 256, SMEM_BYTES>>>(In, WQ, WK);

    finalize_kernel<<<1, 256>>>(out);
}

// round 9
// speedup vs baseline: 1.6188x; 1.6188x over previous
#include <cuda_runtime.h>
#include <cuda_bf16.h>
#include <cstdint>

#define S_LEN  262144
#define NDIM   128
#define TILE   128
#define NTILES 2048
#define NCTA   296        // 2 CTAs/SM x 148 SMs
#define NPROD  128        // producer CTAs for W

// ---------------- device scratch ----------------
__device__ __align__(16) __nv_bfloat16 g_Bsw[NDIM * NDIM];  // B[t][k]=bf16(M[k][t]), swizzled
__device__ float g_partials[NCTA];
__device__ float g_l1part[NPROD];
__device__ int   g_done;                                     // producer counter (reset by finalize)

// ---------------- smem byte offsets (per CTA ~99KB -> 2 CTAs/SM) ----------------
#define STG   0          // fp32 staging: 128 x 512B = 65536 (single buffer)
#define BOF   65536      // B bf16 swizzled: 32768
#define RED   98304      // reduction: 256 fp32 (aliases producer l1 scratch)
#define SMEM_BYTES 99328

// ---------------- helpers ----------------
__device__ __forceinline__ uint32_t smem_u32(const void* p) {
    uint32_t a;
    asm("{ .reg .u64 t; cvta.to.shared.u64 t, %1; cvt.u32.u64 %0, t; }" : "=r"(a) : "l"(p));
    return a;
}
__device__ __forceinline__ uint32_t bf2(float xh, float xl) {
    uint32_t r;
    asm("cvt.rn.bf16x2.f32 %0, %1, %2;" : "=r"(r) : "f"(xh), "f"(xl));
    return r;
}
__device__ __forceinline__ float4 lds128f(uint32_t a) {
    float4 v;
    asm volatile("ld.shared.v4.f32 {%0,%1,%2,%3}, [%4];"
                 : "=f"(v.x), "=f"(v.y), "=f"(v.z), "=f"(v.w) : "r"(a));
    return v;
}
__device__ __forceinline__ uint2 lds64u(uint32_t a) {
    uint2 v;
    asm volatile("ld.shared.v2.b32 {%0,%1}, [%2];" : "=r"(v.x), "=r"(v.y) : "r"(a));
    return v;
}
__device__ __forceinline__ void cpa16(uint32_t dst, const void* src) {
    asm volatile("cp.async.cg.shared.global [%0], [%1], 16;" :: "r"(dst), "l"(src));
}
__device__ __forceinline__ void cpa_commit() { asm volatile("cp.async.commit_group;" ::: "memory"); }
__device__ __forceinline__ void cpa_wait0()  { asm volatile("cp.async.wait_group 0;" ::: "memory"); }

__device__ __forceinline__ void mma_bf16(float* d, const uint32_t* a, uint32_t b0, uint32_t b1) {
    asm volatile(
        "mma.sync.aligned.m16n8k16.row.col.f32.bf16.bf16.f32 "
        "{%0,%1,%2,%3}, {%4,%5,%6,%7}, {%8,%9}, {%0,%1,%2,%3};"
        : "+f"(d[0]), "+f"(d[1]), "+f"(d[2]), "+f"(d[3])
        : "r"(a[0]), "r"(a[1]), "r"(a[2]), "r"(a[3]), "r"(b0), "r"(b1));
}
__device__ __forceinline__ float softplusf(float x) {
    const float l = __logf(1.0f + __expf(x));
    return (x > 15.0f) ? x : l;
}
// swizzled byte offset: plane row t (256B rows), element index k
__device__ __forceinline__ uint32_t gsw(int t, int k) {
    return (uint32_t)(t * 256 + (((k >> 2) ^ ((t & 7) << 2)) << 3) + (k & 3) * 2);
}

// ---------------- fused persistent kernel ----------------
extern __shared__ char dsm[];

__device__ __forceinline__ void issue_prefetch(const float* __restrict__ In, int tile,
                                               uint32_t sb, int tid) {
    const char* src = (const char*)(In + (size_t)tile * TILE * NDIM);
#pragma unroll
    for (int j = 0; j < 16; ++j) {
        const int idx = tid + 256 * j;           // 4096 16B chunks
        const int r = idx >> 5, c = idx & 31;
        cpa16(sb + STG + r * 512 + ((c ^ ((r & 1) << 2)) << 4), src + r * 512 + c * 16);
    }
    cpa_commit();
}

__global__ void __launch_bounds__(256, 2)
fused_kernel(const float* __restrict__ In, const float* __restrict__ WQ,
             const float* __restrict__ WK) {
    const uint32_t sb = smem_u32(dsm);
    const int tid  = threadIdx.x;
    const int lane = tid & 31;
    const int w    = tid >> 5;
    const int m0   = (w & 3) << 5;     // warp tile: 32m x 64n (grid 4m x 2n)
    const int n0   = (w >> 2) << 6;
    const int g    = lane >> 2;
    const int q    = lane & 3;
    const int bx   = blockIdx.x;

    // first tile prefetch ASAP (async; overlaps producer phase below)
    issue_prefetch(In, bx, sb, tid);

    // ---- producers: CTA c < NPROD computes column c of M, emits B row + l1 partial ----
    if (bx < NPROD) {
        const int c  = bx;
        const int i  = tid >> 1;      // M row index (k)
        const int jh = tid & 1;
        float acc = 0.f;
#pragma unroll 8
        for (int jj = 0; jj < 64; ++jj) {
            const int j = jh * 64 + jj;
            acc = fmaf(__ldg(WK + j * NDIM + i), __ldg(WQ + j * NDIM + c), acc);
        }
        acc += __shfl_xor_sync(0xffffffffu, acc, 1);
        float* sL1 = (float*)(dsm + RED);
        if (jh == 0) {
            *(__nv_bfloat16*)((char*)g_Bsw + gsw(c, i)) = __float2bfloat16(acc);
            sL1[i] = 1.0f / (1.0f + __expf(-acc));      // sigmoid(M[i][c])
        }
        __syncthreads();
        // deterministic tree reduce of 128 sigmoids
        for (int o = 64; o; o >>= 1) {
            if (tid < o) sL1[tid] += sL1[tid + o];
            __syncthreads();
        }
        if (tid == 0) g_l1part[c] = sL1[0];
        __threadfence();
        __syncthreads();
        if (tid == 0) atomicAdd(&g_done, 1);
    }

    // ---- wait for all producers, then stage B ----
    if (tid == 0) {
        int v;
        do {
            asm volatile("ld.acquire.gpu.b32 %0, [%1];" : "=r"(v) : "l"(&g_done) : "memory");
            if (v < NPROD) __nanosleep(64);
        } while (v < NPROD);
    }
    __syncthreads();
    {
        const float4* src = (const float4*)g_Bsw;
        float4* dst = (float4*)(dsm + BOF);
#pragma unroll
        for (int k = tid; k < 2048; k += 256) dst[k] = src[k];
    }

    const int rA0 = m0 + g;
    const uint32_t xA = (uint32_t)((g & 1) << 2);
    const uint32_t xB = (uint32_t)(g << 2);
    const uint32_t bA = sb + STG + (uint32_t)rA0 * 512;
    const uint32_t bB = sb + BOF + (uint32_t)(n0 + g) * 256;

    const int nt = (NTILES - bx + NCTA - 1) / NCTA;
    float loss = 0.f;

    for (int i = 0; i < nt; ++i) {
        const int tile = bx + i * NCTA;
        cpa_wait0();
        __syncthreads();                 // staging + (first iter) B ready

        float dacc[2][8][4];
#pragma unroll
        for (int mh = 0; mh < 2; ++mh)
#pragma unroll
            for (int nf = 0; nf < 8; ++nf)
#pragma unroll
                for (int j = 0; j < 4; ++j) dacc[mh][nf][j] = 0.f;
        float rsum[4] = {0.f, 0.f, 0.f, 0.f};

#pragma unroll
        for (int ks = 0; ks < 8; ++ks) {
            const uint32_t c = (uint32_t)(4 * ks + q);
            const uint32_t offA = ((c ^ xA) << 4);
            const float4 v00 = lds128f(bA + offA);               // row rA0
            const float4 v01 = lds128f(bA + 8 * 512 + offA);     // row rA0+8
            const float4 v10 = lds128f(bA + 16 * 512 + offA);    // row rA0+16
            const float4 v11 = lds128f(bA + 24 * 512 + offA);    // row rA0+24
            rsum[0] += (v00.x + v00.y) + (v00.z + v00.w);
            rsum[1] += (v01.x + v01.y) + (v01.z + v01.w);
            rsum[2] += (v10.x + v10.y) + (v10.z + v10.w);
            rsum[3] += (v11.x + v11.y) + (v11.z + v11.w);
            uint32_t a0[4], a1[4];
            a0[0] = bf2(v00.y, v00.x); a0[1] = bf2(v01.y, v01.x);
            a0[2] = bf2(v00.w, v00.z); a0[3] = bf2(v01.w, v01.z);
            a1[0] = bf2(v10.y, v10.x); a1[1] = bf2(v11.y, v11.x);
            a1[2] = bf2(v10.w, v10.z); a1[3] = bf2(v11.w, v11.z);
            const uint32_t offB = ((c ^ xB) << 3);
#pragma unroll
            for (int nf = 0; nf < 8; ++nf) {
                const uint2 b = lds64u(bB + (uint32_t)nf * 2048 + offB);
                mma_bf16(dacc[0][nf], a0, b.x, b.y);
                mma_bf16(dacc[1][nf], a1, b.x, b.y);
            }
        }

        __syncthreads();                 // all warps done reading staging
        if (i + 1 < nt) issue_prefetch(In, bx + (i + 1) * NCTA, sb, tid);   // overlaps epilogue

        // quad-reduce rowsums
#pragma unroll
        for (int j = 0; j < 4; ++j) {
            rsum[j] += __shfl_xor_sync(0xffffffffu, rsum[j], 1);
            rsum[j] += __shfl_xor_sync(0xffffffffu, rsum[j], 2);
        }

        // -------- epilogue: targets from L2 (Input is cp.async-hot) --------
        const size_t base = (size_t)tile * TILE;
#pragma unroll
        for (int mh = 0; mh < 2; ++mh) {
            const int rA = m0 + 16 * mh + g;        // <= 119 (row rA always valid)
            const int rB = rA + 8;                  // <= 127
            const float rsA = rsum[2 * mh];
            const float rsB = rsum[2 * mh + 1];
            const bool vB = (base + rB) < (size_t)(S_LEN - 1);
            const float2* pA = (const float2*)(In + (base + rA + 1) * NDIM);
            const float2* pB = vB ? (const float2*)(In + (base + rB + 1) * NDIM) : pA;
#pragma unroll
            for (int nf = 0; nf < 8; ++nf) {
                const int col0 = n0 + 8 * nf + 2 * q;
                const float2 nxa = __ldg(pA + (col0 >> 1));
                const float* d = dacc[mh][nf];
                const float t0 = fmaf(softplusf(d[0]), rsA, -nxa.x);
                const float t1 = fmaf(softplusf(d[1]), rsA, -nxa.y);
                loss = fmaf(t0, t0, loss);
                loss = fmaf(t1, t1, loss);
                if (vB) {
                    const float2 nxb = __ldg(pB + (col0 >> 1));
                    const float t2 = fmaf(softplusf(d[2]), rsB, -nxb.x);
                    const float t3 = fmaf(softplusf(d[3]), rsB, -nxb.y);
                    loss = fmaf(t2, t2, loss);
                    loss = fmaf(t3, t3, loss);
                }
            }
        }
    }

    // deterministic CTA reduction
    float* sRed = (float*)(dsm + RED);
    __syncthreads();                      // producers' l1 scratch long dead; safe reuse
    sRed[tid] = loss;
    __syncthreads();
#pragma unroll
    for (int o = 128; o; o >>= 1) {
        if (tid < o) sRed[tid] += sRed[tid + o];
        __syncthreads();
    }
    if (tid == 0) g_partials[bx] = sRed[0];
}

// ---------------- finalize: tiny deterministic reduce ----------------
__global__ void finalize_kernel(float* __restrict__ out) {
    __shared__ double red[256];
    const int tid = threadIdx.x;

    double s = 0.0;
    for (int k = tid; k < NCTA; k += 256) s += (double)g_partials[k];
    red[tid] = s;
    __syncthreads();
    for (int o = 128; o; o >>= 1) {
        if (tid < o) red[tid] += red[tid + o];
        __syncthreads();
    }
    if (tid == 0)
        out[0] = (float)(red[0] / ((double)(S_LEN - 1) * (double)NDIM));
    __syncthreads();

    red[tid] = (tid < NPROD) ? (double)g_l1part[tid] : 0.0;
    __syncthreads();
    for (int o = 128; o; o >>= 1) {
        if (tid < o) red[tid] += red[tid + o];
        __syncthreads();
    }
    if (tid == 0) {
        out[1] = (float)red[0];
        g_done = 0;                      // reset for next graph replay
    }
}

// ---------------- launch ----------------
extern "C" void kernel_launch(void* const* d_in, const int* in_sizes, int n_in,
                              void* d_out, int out_size) {
    const float* In = (const float*)d_in[0];
    const float* WQ = (const float*)d_in[1];
    const float* WK = (const float*)d_in[2];
    float* out = (float*)d_out;

    cudaFuncSetAttribute(fused_kernel,
                         cudaFuncAttributeMaxDynamicSharedMemorySize, SMEM_BYTES);
    fused_kernel<<<NCTA, 256, SMEM_BYTES>>>(In, WQ, WK);

    finalize_kernel<<<1, 256>>>(out);
}